// round 12
// baseline (speedup 1.0000x reference)
#include <cuda_runtime.h>
#include <cuda_bf16.h>
#include <math.h>
#include <stdint.h>

#define Bc 4
#define Sc 1024
#define DIMc 1024
#define Hc 16
#define DHc 64
#define Mc (Bc * Sc)

// ---------------- scratch (__device__ globals; no allocation allowed) -------
__device__ float g_q[Mc * DIMc];
__device__ float g_k[Mc * DIMc];
__device__ float g_cs[Sc * 32];
__device__ float g_sn[Sc * 32];
__device__ __nv_bfloat16 g_xhi[Mc * DIMc];
__device__ __nv_bfloat16 g_xlo[Mc * DIMc];
__device__ __nv_bfloat16 g_whi[4 * DIMc * DIMc];
__device__ __nv_bfloat16 g_wlo[4 * DIMc * DIMc];
__device__ __nv_bfloat16 g_qhi[Mc * DIMc];
__device__ __nv_bfloat16 g_qlo[Mc * DIMc];
__device__ __nv_bfloat16 g_khi[Mc * DIMc];
__device__ __nv_bfloat16 g_klo[Mc * DIMc];
__device__ __nv_bfloat16 g_vhi[Mc * DIMc];
__device__ __nv_bfloat16 g_vlo[Mc * DIMc];
__device__ __nv_bfloat16 g_ohi[Mc * DIMc];
__device__ __nv_bfloat16 g_olo[Mc * DIMc];

// ---------------- PTX helpers (non-'a' features only) -----------------------
__device__ __forceinline__ uint32_t smem_u32(const void* p) {
  uint32_t a;
  asm("{ .reg .u64 t; cvta.to.shared.u64 t, %1; cvt.u32.u64 %0, t; }"
      : "=r"(a) : "l"(p));
  return a;
}

__device__ __forceinline__ void cpa16(uint32_t dst, const void* src) {
  asm volatile("cp.async.ca.shared.global [%0], [%1], 16;" ::"r"(dst),
               "l"(src));
}
#define CP_COMMIT asm volatile("cp.async.commit_group;" ::: "memory")
#define CP_WAIT1 asm volatile("cp.async.wait_group 1;" ::: "memory")
#define CP_WAIT0 asm volatile("cp.async.wait_group 0;" ::: "memory")

__device__ __forceinline__ void ldm_x4(uint32_t addr, uint32_t* r) {
  asm volatile(
      "ldmatrix.sync.aligned.m8n8.x4.shared.b16 {%0,%1,%2,%3}, [%4];"
      : "=r"(r[0]), "=r"(r[1]), "=r"(r[2]), "=r"(r[3])
      : "r"(addr));
}

__device__ __forceinline__ void ldm_x4_trans(uint32_t addr, uint32_t* r) {
  asm volatile(
      "ldmatrix.sync.aligned.m8n8.x4.trans.shared.b16 {%0,%1,%2,%3}, [%4];"
      : "=r"(r[0]), "=r"(r[1]), "=r"(r[2]), "=r"(r[3])
      : "r"(addr));
}

__device__ __forceinline__ void mma16816(float* c, const uint32_t* a,
                                         const uint32_t* b) {
  asm volatile(
      "mma.sync.aligned.m16n8k16.row.col.f32.bf16.bf16.f32 "
      "{%0,%1,%2,%3}, {%4,%5,%6,%7}, {%8,%9}, {%0,%1,%2,%3};"
      : "+f"(c[0]), "+f"(c[1]), "+f"(c[2]), "+f"(c[3])
      : "r"(a[0]), "r"(a[1]), "r"(a[2]), "r"(a[3]), "r"(b[0]), "r"(b[1]));
}

__device__ __forceinline__ uint32_t packbf(float a, float b) {
  __nv_bfloat162 t(__float2bfloat16(a), __float2bfloat16(b));
  return *(uint32_t*)&t;
}

// ---------------- split kernels (fp32 -> bf16 hi/lo) ------------------------
__global__ void __launch_bounds__(256) split_kernel(
    const float* __restrict__ src, __nv_bfloat16* __restrict__ hi,
    __nv_bfloat16* __restrict__ lo, int n4) {
  int i = blockIdx.x * blockDim.x + threadIdx.x;
  if (i >= n4) return;
  float4 v = ((const float4*)src)[i];
  __nv_bfloat16 h0 = __float2bfloat16(v.x);
  __nv_bfloat16 h1 = __float2bfloat16(v.y);
  __nv_bfloat16 h2 = __float2bfloat16(v.z);
  __nv_bfloat16 h3 = __float2bfloat16(v.w);
  __nv_bfloat162* hp = (__nv_bfloat162*)hi;
  __nv_bfloat162* lp = (__nv_bfloat162*)lo;
  hp[2 * i] = __nv_bfloat162(h0, h1);
  hp[2 * i + 1] = __nv_bfloat162(h2, h3);
  lp[2 * i] = __nv_bfloat162(__float2bfloat16(v.x - __bfloat162float(h0)),
                             __float2bfloat16(v.y - __bfloat162float(h1)));
  lp[2 * i + 1] = __nv_bfloat162(__float2bfloat16(v.z - __bfloat162float(h2)),
                                 __float2bfloat16(v.w - __bfloat162float(h3)));
}

__global__ void __launch_bounds__(256) split_w_kernel(
    const float* __restrict__ Wq, const float* __restrict__ Wk,
    const float* __restrict__ Wv, const float* __restrict__ Wo) {
  int slot = blockIdx.y;
  const float* W = (slot == 0) ? Wq : (slot == 1) ? Wk : (slot == 2) ? Wv : Wo;
  int i = blockIdx.x * blockDim.x + threadIdx.x;
  int n4 = DIMc * DIMc / 4;
  if (i >= n4) return;
  float4 v = ((const float4*)W)[i];
  __nv_bfloat16* hi = g_whi + (size_t)slot * DIMc * DIMc;
  __nv_bfloat16* lo = g_wlo + (size_t)slot * DIMc * DIMc;
  __nv_bfloat16 h0 = __float2bfloat16(v.x);
  __nv_bfloat16 h1 = __float2bfloat16(v.y);
  __nv_bfloat16 h2 = __float2bfloat16(v.z);
  __nv_bfloat16 h3 = __float2bfloat16(v.w);
  __nv_bfloat162* hp = (__nv_bfloat162*)hi;
  __nv_bfloat162* lp = (__nv_bfloat162*)lo;
  hp[2 * i] = __nv_bfloat162(h0, h1);
  hp[2 * i + 1] = __nv_bfloat162(h2, h3);
  lp[2 * i] = __nv_bfloat162(__float2bfloat16(v.x - __bfloat162float(h0)),
                             __float2bfloat16(v.y - __bfloat162float(h1)));
  lp[2 * i + 1] = __nv_bfloat162(__float2bfloat16(v.z - __bfloat162float(h2)),
                                 __float2bfloat16(v.w - __bfloat162float(h3)));
}

// ---------------- HMMA split-bf16 GEMM --------------------------------------
#define ASTRIDE_B 80
#define TILE_B (128 * ASTRIDE_B)
#define STAGE_B (4 * TILE_B)
#define G_SMEM (2 * STAGE_B)

__device__ __forceinline__ void load_stage(
    uint32_t sbase, const __nv_bfloat16* __restrict__ Ahi,
    const __nv_bfloat16* __restrict__ Alo, const __nv_bfloat16* __restrict__ Bhi,
    const __nv_bfloat16* __restrict__ Blo, int row0, int col0, int k0,
    int tid) {
  const __nv_bfloat16* srcs[4];
  srcs[0] = Ahi + (size_t)row0 * DIMc;
  srcs[1] = Alo + (size_t)row0 * DIMc;
  srcs[2] = Bhi + (size_t)col0 * DIMc;
  srcs[3] = Blo + (size_t)col0 * DIMc;
#pragma unroll
  for (int tbl = 0; tbl < 4; tbl++) {
    const __nv_bfloat16* s = srcs[tbl];
    uint32_t dst = sbase + tbl * TILE_B;
#pragma unroll
    for (int it = 0; it < 2; it++) {
      int idx = tid + it * 256;
      int row = idx >> 2, c = idx & 3;
      cpa16(dst + row * ASTRIDE_B + c * 16,
            s + (size_t)row * DIMc + k0 + c * 8);
    }
  }
}

template <int OUTS>
__device__ __forceinline__ void gemm_tc_body(
    const __nv_bfloat16* __restrict__ Ahi, const __nv_bfloat16* __restrict__ Alo,
    const __nv_bfloat16* __restrict__ Whi, const __nv_bfloat16* __restrict__ Wlo,
    const float* __restrict__ bias, float* __restrict__ C,
    __nv_bfloat16* __restrict__ Chi, __nv_bfloat16* __restrict__ Clo) {
  extern __shared__ char smg[];
  uint32_t sb = smem_u32(smg);
  const int tid = threadIdx.x;
  const int lane = tid & 31, wid = tid >> 5;
  const int warpm = wid & 3, warpn = wid >> 2;
  const int row0 = blockIdx.y * 128, col0 = blockIdx.x * 128;

  float acc[2][8][4];
#pragma unroll
  for (int mt = 0; mt < 2; mt++)
#pragma unroll
    for (int j = 0; j < 8; j++)
#pragma unroll
      for (int c = 0; c < 4; c++) acc[mt][j][c] = 0.f;

  const int a_row = lane & 15, a_kof = (lane >> 4) * 8;
  const int b_n = (lane & 7) + ((lane >> 4) * 8);
  const int b_kof = ((lane >> 3) & 1) * 8;

  load_stage(sb, Ahi, Alo, Whi, Wlo, row0, col0, 0, tid);
  CP_COMMIT;

  const int T = DIMc / 32;
  for (int t = 0; t < T; t++) {
    if (t + 1 < T) {
      load_stage(sb + ((t + 1) & 1) * STAGE_B, Ahi, Alo, Whi, Wlo, row0, col0,
                 (t + 1) * 32, tid);
      CP_COMMIT;
      CP_WAIT1;
    } else {
      CP_WAIT0;
    }
    __syncthreads();

    uint32_t st = sb + (t & 1) * STAGE_B;
    uint32_t Ahs = st, Als = st + TILE_B, Bhs = st + 2 * TILE_B,
             Bls = st + 3 * TILE_B;
#pragma unroll
    for (int kk = 0; kk < 32; kk += 16) {
      uint32_t ah[2][4], al[2][4];
#pragma unroll
      for (int mt = 0; mt < 2; mt++) {
        int r = warpm * 32 + mt * 16 + a_row;
        uint32_t off = r * ASTRIDE_B + (kk + a_kof) * 2;
        ldm_x4(Ahs + off, ah[mt]);
        ldm_x4(Als + off, al[mt]);
      }
#pragma unroll
      for (int nt = 0; nt < 4; nt++) {
        uint32_t bh[4], bl[4];
        int n = warpn * 64 + nt * 16 + b_n;
        uint32_t off = n * ASTRIDE_B + (kk + b_kof) * 2;
        ldm_x4(Bhs + off, bh);
        ldm_x4(Bls + off, bl);
        // Reordered: same-accumulator MMAs are 4 apart (latency hiding),
        // per-accumulator product order stays hh -> hl -> lh (bit-identical).
        mma16816(acc[0][nt * 2 + 0], ah[0], &bh[0]);
        mma16816(acc[0][nt * 2 + 1], ah[0], &bh[2]);
        mma16816(acc[1][nt * 2 + 0], ah[1], &bh[0]);
        mma16816(acc[1][nt * 2 + 1], ah[1], &bh[2]);
        mma16816(acc[0][nt * 2 + 0], ah[0], &bl[0]);
        mma16816(acc[0][nt * 2 + 1], ah[0], &bl[2]);
        mma16816(acc[1][nt * 2 + 0], ah[1], &bl[0]);
        mma16816(acc[1][nt * 2 + 1], ah[1], &bl[2]);
        mma16816(acc[0][nt * 2 + 0], al[0], &bh[0]);
        mma16816(acc[0][nt * 2 + 1], al[0], &bh[2]);
        mma16816(acc[1][nt * 2 + 0], al[1], &bh[0]);
        mma16816(acc[1][nt * 2 + 1], al[1], &bh[2]);
      }
    }
    __syncthreads();
  }

#pragma unroll
  for (int mt = 0; mt < 2; mt++) {
#pragma unroll
    for (int j = 0; j < 8; j++) {
      int row = row0 + warpm * 32 + mt * 16 + (lane >> 2);
      int col = col0 + warpn * 64 + j * 8 + (lane & 3) * 2;
      float b0 = bias[col], b1 = bias[col + 1];
      float x0 = acc[mt][j][0] + b0, x1 = acc[mt][j][1] + b1;
      float y0 = acc[mt][j][2] + b0, y1 = acc[mt][j][3] + b1;
      if (OUTS) {
        __nv_bfloat16 h0 = __float2bfloat16(x0), h1 = __float2bfloat16(x1);
        __nv_bfloat16 g0 = __float2bfloat16(y0), g1 = __float2bfloat16(y1);
        *(__nv_bfloat162*)(Chi + (size_t)row * DIMc + col) =
            __nv_bfloat162(h0, h1);
        *(__nv_bfloat162*)(Clo + (size_t)row * DIMc + col) = __nv_bfloat162(
            __float2bfloat16(x0 - __bfloat162float(h0)),
            __float2bfloat16(x1 - __bfloat162float(h1)));
        *(__nv_bfloat162*)(Chi + (size_t)(row + 8) * DIMc + col) =
            __nv_bfloat162(g0, g1);
        *(__nv_bfloat162*)(Clo + (size_t)(row + 8) * DIMc + col) =
            __nv_bfloat162(__float2bfloat16(y0 - __bfloat162float(g0)),
                           __float2bfloat16(y1 - __bfloat162float(g1)));
      } else {
        *(float2*)(C + (size_t)row * DIMc + col) = make_float2(x0, x1);
        *(float2*)(C + (size_t)(row + 8) * DIMc + col) = make_float2(y0, y1);
      }
    }
  }
}

__global__ void __launch_bounds__(256, 2) gemm_tc_qkv(
    const float* __restrict__ bq, const float* __restrict__ bk,
    const float* __restrict__ bv, float* __restrict__ Cq,
    float* __restrict__ Ck) {
  int z = blockIdx.z;
  const __nv_bfloat16* Whi = g_whi + (size_t)z * DIMc * DIMc;
  const __nv_bfloat16* Wlo = g_wlo + (size_t)z * DIMc * DIMc;
  if (z == 2) {
    gemm_tc_body<1>(g_xhi, g_xlo, Whi, Wlo, bv, nullptr, g_vhi, g_vlo);
  } else {
    const float* bias = (z == 0) ? bq : bk;
    float* C = (z == 0) ? Cq : Ck;
    gemm_tc_body<0>(g_xhi, g_xlo, Whi, Wlo, bias, C, nullptr, nullptr);
  }
}

__global__ void __launch_bounds__(256, 2) gemm_tc_out(
    const float* __restrict__ bo, float* __restrict__ C) {
  const __nv_bfloat16* Whi = g_whi + (size_t)3 * DIMc * DIMc;
  const __nv_bfloat16* Wlo = g_wlo + (size_t)3 * DIMc * DIMc;
  gemm_tc_body<0>(g_ohi, g_olo, Whi, Wlo, bo, C, nullptr, nullptr);
}

// ---------------- RoPE: fp32 in, split bf16 out -----------------------------
__global__ void rope_table_kernel() {
  int idx = blockIdx.x * blockDim.x + threadIdx.x;
  if (idx >= Sc * 32) return;
  int j = idx & 31;
  int s = idx >> 5;
  double freq = exp(-(double)j * (log(10000.0) / 32.0));
  double ang = (double)s * freq;
  g_cs[idx] = (float)cos(ang);
  g_sn[idx] = (float)sin(ang);
}

__device__ __forceinline__ void split_store(__nv_bfloat16* hi,
                                            __nv_bfloat16* lo, size_t off,
                                            float v) {
  __nv_bfloat16 h = __float2bfloat16(v);
  hi[off] = h;
  lo[off] = __float2bfloat16(v - __bfloat162float(h));
}

__global__ void __launch_bounds__(256) rope_apply_kernel(
    const float* __restrict__ q, const float* __restrict__ k) {
  int idx = blockIdx.x * blockDim.x + threadIdx.x;
  if (idx >= Mc * Hc * 32) return;
  int j = idx & 31;
  int h = (idx >> 5) & (Hc - 1);
  int m = idx >> 9;
  int s = m & (Sc - 1);
  float cs = g_cs[s * 32 + j];
  float sn = g_sn[s * 32 + j];
  size_t base = (size_t)m * DIMc + h * DHc;
  float q1 = q[base + j], q2 = q[base + j + 32];
  float qr1 = fmaf(q1, cs, -q2 * sn);
  float qr2 = fmaf(q2, cs, q1 * sn);
  split_store(g_qhi, g_qlo, base + j, qr1);
  split_store(g_qhi, g_qlo, base + j + 32, qr2);
  float k1 = k[base + j], k2 = k[base + j + 32];
  float kr1 = fmaf(k1, cs, -k2 * sn);
  float kr2 = fmaf(k2, cs, k1 * sn);
  split_store(g_khi, g_klo, base + j, kr1);
  split_store(g_khi, g_klo, base + j + 32, kr2);
}

// ---------------- Flash attention, HMMA, double-buffered KV -----------------
// Block: 128 q-rows x one (b,h). 8 warps. KV tile 64, 2-stage cp.async.
#define FSTR 72
#define FB (FSTR * 2)
// element offsets
#define F_QH 0
#define F_QL 9216
#define F_KV0 18432
#define KV_STAGE_E 18432  // 4 arrays x 64 x 72
#define F_SMEM_B ((18432 + 2 * 18432) * 2)  // 110592 B

__device__ __forceinline__ void flash_kv_load(uint32_t stgA, size_t kvof,
                                              int tid) {
#pragma unroll
  for (int it = 0; it < 8; it++) {
    int idx = tid + it * 256;
    int arr = idx >> 9, rem = idx & 511;
    int row = rem >> 3, c = rem & 7;
    const __nv_bfloat16* src =
        (arr == 0) ? g_khi : (arr == 1) ? g_klo : (arr == 2) ? g_vhi : g_vlo;
    uint32_t dstA = stgA + arr * (4608 * 2);
    cpa16(dstA + row * FB + c * 16, src + kvof + (size_t)row * DIMc + c * 8);
  }
}

__global__ void __launch_bounds__(256, 2) flash_tc_kernel() {
  extern __shared__ __nv_bfloat16 sf[];
  uint32_t sbase = smem_u32(sf);
  const uint32_t QhA = sbase + F_QH * 2, QlA = sbase + F_QL * 2;

  const int tid = threadIdx.x, lane = tid & 31, w = tid >> 5;
  const int b = blockIdx.y >> 4, h = blockIdx.y & 15;
  const int q0 = blockIdx.x * 128;
  const size_t hof = (size_t)b * Sc * DIMc + h * DHc;

  // Q tiles (hi+lo) via cp.async
#pragma unroll
  for (int it = 0; it < 4; it++) {
    int idx = tid + it * 256;
    int row = idx >> 3, c = idx & 7;
    cpa16(QhA + row * FB + c * 16, g_qhi + hof + (size_t)(q0 + row) * DIMc + c * 8);
    cpa16(QlA + row * FB + c * 16, g_qlo + hof + (size_t)(q0 + row) * DIMc + c * 8);
  }
  CP_COMMIT;
  // KV tile 0 into stage 0
  flash_kv_load(sbase + F_KV0 * 2, hof, tid);
  CP_COMMIT;
  CP_WAIT0;
  __syncthreads();

  const int a_row = lane & 15, a_kof = (lane >> 4) * 8;
  const int b_n = (lane & 7) + ((lane >> 4) * 8);
  const int b_kof = ((lane >> 3) & 1) * 8;
  uint32_t qh[4][4], ql[4][4];
#pragma unroll
  for (int kc = 0; kc < 4; kc++) {
    uint32_t off = (uint32_t)(w * 16 + a_row) * FB + (kc * 16 + a_kof) * 2;
    ldm_x4(QhA + off, qh[kc]);
    ldm_x4(QlA + off, ql[kc]);
  }

  float m0 = -INFINITY, m1 = -INFINITY, l0 = 0.f, l1 = 0.f;
  float acc[8][4];
#pragma unroll
  for (int dt = 0; dt < 8; dt++)
#pragma unroll
    for (int c = 0; c < 4; c++) acc[dt][c] = 0.f;

  const float scale = 0.125f;

  for (int t = 0; t < 16; t++) {
    // prefetch next KV tile into the other stage
    if (t + 1 < 16) {
      __syncthreads();  // everyone done reading that stage (iter t-1)
      flash_kv_load(sbase + (F_KV0 + ((t + 1) & 1) * KV_STAGE_E) * 2,
                    hof + (size_t)(t + 1) * 64 * DIMc, tid);
      CP_COMMIT;
      CP_WAIT1;
    } else {
      CP_WAIT0;
    }
    __syncthreads();

    uint32_t stg = sbase + (F_KV0 + (t & 1) * KV_STAGE_E) * 2;
    uint32_t KhA = stg, KlA = stg + 4608 * 2, VhA = stg + 9216 * 2,
             VlA = stg + 13824 * 2;

    // ---- S = Q K^T (warp: 16 x 64), ng pairs, distance-4 reorder
    float s[8][4];
#pragma unroll
    for (int nt = 0; nt < 8; nt++)
#pragma unroll
      for (int c = 0; c < 4; c++) s[nt][c] = 0.f;
#pragma unroll
    for (int kc = 0; kc < 4; kc++) {
#pragma unroll
      for (int ngp = 0; ngp < 4; ngp += 2) {
        uint32_t bha[4], bla[4], bhb[4], blb[4];
        uint32_t offa = (uint32_t)(ngp * 16 + b_n) * FB + (kc * 16 + b_kof) * 2;
        uint32_t offb =
            (uint32_t)((ngp + 1) * 16 + b_n) * FB + (kc * 16 + b_kof) * 2;
        ldm_x4(KhA + offa, bha);
        ldm_x4(KlA + offa, bla);
        ldm_x4(KhA + offb, bhb);
        ldm_x4(KlA + offb, blb);
        float* c0 = s[2 * ngp + 0];
        float* c1 = s[2 * ngp + 1];
        float* c2 = s[2 * ngp + 2];
        float* c3 = s[2 * ngp + 3];
        mma16816(c0, qh[kc], &bha[0]);
        mma16816(c1, qh[kc], &bha[2]);
        mma16816(c2, qh[kc], &bhb[0]);
        mma16816(c3, qh[kc], &bhb[2]);
        mma16816(c0, qh[kc], &bla[0]);
        mma16816(c1, qh[kc], &bla[2]);
        mma16816(c2, qh[kc], &blb[0]);
        mma16816(c3, qh[kc], &blb[2]);
        mma16816(c0, ql[kc], &bha[0]);
        mma16816(c1, ql[kc], &bha[2]);
        mma16816(c2, ql[kc], &bhb[0]);
        mma16816(c3, ql[kc], &bhb[2]);
      }
    }

    // ---- online softmax
    float mx0 = -INFINITY, mx1 = -INFINITY;
#pragma unroll
    for (int nt = 0; nt < 8; nt++) {
      s[nt][0] *= scale; s[nt][1] *= scale;
      s[nt][2] *= scale; s[nt][3] *= scale;
      mx0 = fmaxf(mx0, fmaxf(s[nt][0], s[nt][1]));
      mx1 = fmaxf(mx1, fmaxf(s[nt][2], s[nt][3]));
    }
    mx0 = fmaxf(mx0, __shfl_xor_sync(0xffffffffu, mx0, 1));
    mx0 = fmaxf(mx0, __shfl_xor_sync(0xffffffffu, mx0, 2));
    mx1 = fmaxf(mx1, __shfl_xor_sync(0xffffffffu, mx1, 1));
    mx1 = fmaxf(mx1, __shfl_xor_sync(0xffffffffu, mx1, 2));
    float mn0 = fmaxf(m0, mx0), mn1 = fmaxf(m1, mx1);
    float corr0 = __expf(m0 - mn0), corr1 = __expf(m1 - mn1);
    m0 = mn0; m1 = mn1;
    float rs0 = 0.f, rs1 = 0.f;
#pragma unroll
    for (int nt = 0; nt < 8; nt++) {
      s[nt][0] = __expf(s[nt][0] - mn0);
      s[nt][1] = __expf(s[nt][1] - mn0);
      s[nt][2] = __expf(s[nt][2] - mn1);
      s[nt][3] = __expf(s[nt][3] - mn1);
      rs0 += s[nt][0] + s[nt][1];
      rs1 += s[nt][2] + s[nt][3];
    }
    rs0 += __shfl_xor_sync(0xffffffffu, rs0, 1);
    rs0 += __shfl_xor_sync(0xffffffffu, rs0, 2);
    rs1 += __shfl_xor_sync(0xffffffffu, rs1, 1);
    rs1 += __shfl_xor_sync(0xffffffffu, rs1, 2);
    l0 = l0 * corr0 + rs0;
    l1 = l1 * corr1 + rs1;

    // P hi/lo fragments
    uint32_t ph[4][4], pl[4][4];
#pragma unroll
    for (int kc = 0; kc < 4; kc++) {
      float* sa = s[2 * kc];
      float* sbn = s[2 * kc + 1];
      float r0a = __bfloat162float(__float2bfloat16(sa[0]));
      float r0b = __bfloat162float(__float2bfloat16(sa[1]));
      float r1a = __bfloat162float(__float2bfloat16(sa[2]));
      float r1b = __bfloat162float(__float2bfloat16(sa[3]));
      float n0a = __bfloat162float(__float2bfloat16(sbn[0]));
      float n0b = __bfloat162float(__float2bfloat16(sbn[1]));
      float n1a = __bfloat162float(__float2bfloat16(sbn[2]));
      float n1b = __bfloat162float(__float2bfloat16(sbn[3]));
      ph[kc][0] = packbf(sa[0], sa[1]);
      ph[kc][1] = packbf(sa[2], sa[3]);
      ph[kc][2] = packbf(sbn[0], sbn[1]);
      ph[kc][3] = packbf(sbn[2], sbn[3]);
      pl[kc][0] = packbf(sa[0] - r0a, sa[1] - r0b);
      pl[kc][1] = packbf(sa[2] - r1a, sa[3] - r1b);
      pl[kc][2] = packbf(sbn[0] - n0a, sbn[1] - n0b);
      pl[kc][3] = packbf(sbn[2] - n1a, sbn[3] - n1b);
    }

#pragma unroll
    for (int dt = 0; dt < 8; dt++) {
      acc[dt][0] *= corr0; acc[dt][1] *= corr0;
      acc[dt][2] *= corr1; acc[dt][3] *= corr1;
    }

    // ---- O += P V : trans fragments, ng pairs, distance-4 reorder
#pragma unroll
    for (int kc = 0; kc < 4; kc++) {
#pragma unroll
      for (int ngp = 0; ngp < 4; ngp += 2) {
        uint32_t vha[4], vla[4], vhb[4], vlb[4];
        uint32_t offa = (uint32_t)(kc * 16 + (lane & 15)) * FB +
                        (ngp * 16 + (lane >> 4) * 8) * 2;
        uint32_t offb = (uint32_t)(kc * 16 + (lane & 15)) * FB +
                        ((ngp + 1) * 16 + (lane >> 4) * 8) * 2;
        ldm_x4_trans(VhA + offa, vha);
        ldm_x4_trans(VlA + offa, vla);
        ldm_x4_trans(VhA + offb, vhb);
        ldm_x4_trans(VlA + offb, vlb);
        float* c0 = acc[2 * ngp + 0];
        float* c1 = acc[2 * ngp + 1];
        float* c2 = acc[2 * ngp + 2];
        float* c3 = acc[2 * ngp + 3];
        mma16816(c0, ph[kc], &vha[0]);
        mma16816(c1, ph[kc], &vha[2]);
        mma16816(c2, ph[kc], &vhb[0]);
        mma16816(c3, ph[kc], &vhb[2]);
        mma16816(c0, ph[kc], &vla[0]);
        mma16816(c1, ph[kc], &vla[2]);
        mma16816(c2, ph[kc], &vlb[0]);
        mma16816(c3, ph[kc], &vlb[2]);
        mma16816(c0, pl[kc], &vha[0]);
        mma16816(c1, pl[kc], &vha[2]);
        mma16816(c2, pl[kc], &vhb[0]);
        mma16816(c3, pl[kc], &vhb[2]);
      }
    }
  }

  // ---- Writeback directly as hi/lo bf16 (consumed by gemm_tc_out)
  float inv0 = 1.f / l0, inv1 = 1.f / l1;
  int r0 = q0 + w * 16 + (lane >> 2);
#pragma unroll
  for (int dt = 0; dt < 8; dt++) {
    int col = h * DHc + dt * 8 + (lane & 3) * 2;
    float x0 = acc[dt][0] * inv0, x1 = acc[dt][1] * inv0;
    float y0 = acc[dt][2] * inv1, y1 = acc[dt][3] * inv1;
    size_t off0 = (size_t)(b * Sc + r0) * DIMc + col;
    size_t off1 = (size_t)(b * Sc + r0 + 8) * DIMc + col;
    __nv_bfloat16 h0 = __float2bfloat16(x0), h1 = __float2bfloat16(x1);
    __nv_bfloat16 g0 = __float2bfloat16(y0), g1 = __float2bfloat16(y1);
    *(__nv_bfloat162*)(g_ohi + off0) = __nv_bfloat162(h0, h1);
    *(__nv_bfloat162*)(g_olo + off0) =
        __nv_bfloat162(__float2bfloat16(x0 - __bfloat162float(h0)),
                       __float2bfloat16(x1 - __bfloat162float(h1)));
    *(__nv_bfloat162*)(g_ohi + off1) = __nv_bfloat162(g0, g1);
    *(__nv_bfloat162*)(g_olo + off1) =
        __nv_bfloat162(__float2bfloat16(y0 - __bfloat162float(g0)),
                       __float2bfloat16(y1 - __bfloat162float(g1)));
  }
}

// ----------------------------------------------------------------------------
extern "C" void kernel_launch(void* const* d_in, const int* in_sizes, int n_in,
                              void* d_out, int out_size) {
  const float* x = (const float*)d_in[0];
  const float* Wq = (const float*)d_in[1];
  const float* bq = (const float*)d_in[2];
  const float* Wk = (const float*)d_in[3];
  const float* bk = (const float*)d_in[4];
  const float* Wv = (const float*)d_in[5];
  const float* bv = (const float*)d_in[6];
  const float* Wo = (const float*)d_in[7];
  const float* bo = (const float*)d_in[8];
  float* out = (float*)d_out;

  float *qp, *kp;
  cudaGetSymbolAddress((void**)&qp, g_q);
  cudaGetSymbolAddress((void**)&kp, g_k);
  __nv_bfloat16 *xhi, *xlo;
  cudaGetSymbolAddress((void**)&xhi, g_xhi);
  cudaGetSymbolAddress((void**)&xlo, g_xlo);

  cudaFuncSetAttribute(gemm_tc_qkv, cudaFuncAttributeMaxDynamicSharedMemorySize,
                       G_SMEM);
  cudaFuncSetAttribute(gemm_tc_out, cudaFuncAttributeMaxDynamicSharedMemorySize,
                       G_SMEM);
  cudaFuncSetAttribute(flash_tc_kernel,
                       cudaFuncAttributeMaxDynamicSharedMemorySize, F_SMEM_B);

  rope_table_kernel<<<(Sc * 32 + 255) / 256, 256>>>();

  int n4x = Mc * DIMc / 4;
  split_kernel<<<(n4x + 255) / 256, 256>>>(x, xhi, xlo, n4x);
  int n4w = DIMc * DIMc / 4;
  split_w_kernel<<<dim3((n4w + 255) / 256, 4), 256>>>(Wq, Wk, Wv, Wo);

  gemm_tc_qkv<<<dim3(DIMc / 128, Mc / 128, 3), 256, G_SMEM>>>(bq, bk, bv, qp,
                                                              kp);

  int total = Mc * Hc * 32;
  rope_apply_kernel<<<(total + 255) / 256, 256>>>(qp, kp);

  flash_tc_kernel<<<dim3(Sc / 128, Bc * Hc), 256, F_SMEM_B>>>();

  gemm_tc_out<<<dim3(DIMc / 128, Mc / 128), 256, G_SMEM>>>(bo, out);
}

// round 13
// speedup vs baseline: 1.0396x; 1.0396x over previous
#include <cuda_runtime.h>
#include <cuda_bf16.h>
#include <math.h>
#include <stdint.h>

#define Bc 4
#define Sc 1024
#define DIMc 1024
#define Hc 16
#define DHc 64
#define Mc (Bc * Sc)

// ---------------- scratch (__device__ globals; no allocation allowed) -------
__device__ float g_cs[Sc * 32];
__device__ float g_sn[Sc * 32];
__device__ __nv_bfloat16 g_xhi[Mc * DIMc];
__device__ __nv_bfloat16 g_xlo[Mc * DIMc];
__device__ __nv_bfloat16 g_whi[4 * DIMc * DIMc];
__device__ __nv_bfloat16 g_wlo[4 * DIMc * DIMc];
__device__ __nv_bfloat16 g_qhi[Mc * DIMc];
__device__ __nv_bfloat16 g_qlo[Mc * DIMc];
__device__ __nv_bfloat16 g_khi[Mc * DIMc];
__device__ __nv_bfloat16 g_klo[Mc * DIMc];
__device__ __nv_bfloat16 g_vhi[Mc * DIMc];
__device__ __nv_bfloat16 g_vlo[Mc * DIMc];
__device__ __nv_bfloat16 g_ohi[Mc * DIMc];
__device__ __nv_bfloat16 g_olo[Mc * DIMc];

// ---------------- PTX helpers (non-'a' features only) -----------------------
__device__ __forceinline__ uint32_t smem_u32(const void* p) {
  uint32_t a;
  asm("{ .reg .u64 t; cvta.to.shared.u64 t, %1; cvt.u32.u64 %0, t; }"
      : "=r"(a) : "l"(p));
  return a;
}

__device__ __forceinline__ void cpa16(uint32_t dst, const void* src) {
  asm volatile("cp.async.ca.shared.global [%0], [%1], 16;" ::"r"(dst),
               "l"(src));
}
#define CP_COMMIT asm volatile("cp.async.commit_group;" ::: "memory")
#define CP_WAIT1 asm volatile("cp.async.wait_group 1;" ::: "memory")
#define CP_WAIT0 asm volatile("cp.async.wait_group 0;" ::: "memory")

__device__ __forceinline__ void ldm_x4(uint32_t addr, uint32_t* r) {
  asm volatile(
      "ldmatrix.sync.aligned.m8n8.x4.shared.b16 {%0,%1,%2,%3}, [%4];"
      : "=r"(r[0]), "=r"(r[1]), "=r"(r[2]), "=r"(r[3])
      : "r"(addr));
}

__device__ __forceinline__ void ldm_x4_trans(uint32_t addr, uint32_t* r) {
  asm volatile(
      "ldmatrix.sync.aligned.m8n8.x4.trans.shared.b16 {%0,%1,%2,%3}, [%4];"
      : "=r"(r[0]), "=r"(r[1]), "=r"(r[2]), "=r"(r[3])
      : "r"(addr));
}

__device__ __forceinline__ void mma16816(float* c, const uint32_t* a,
                                         const uint32_t* b) {
  asm volatile(
      "mma.sync.aligned.m16n8k16.row.col.f32.bf16.bf16.f32 "
      "{%0,%1,%2,%3}, {%4,%5,%6,%7}, {%8,%9}, {%0,%1,%2,%3};"
      : "+f"(c[0]), "+f"(c[1]), "+f"(c[2]), "+f"(c[3])
      : "r"(a[0]), "r"(a[1]), "r"(a[2]), "r"(a[3]), "r"(b[0]), "r"(b[1]));
}

__device__ __forceinline__ uint32_t packbf(float a, float b) {
  __nv_bfloat162 t(__float2bfloat16(a), __float2bfloat16(b));
  return *(uint32_t*)&t;
}

// ---------------- split kernels (fp32 -> bf16 hi/lo) ------------------------
__global__ void __launch_bounds__(256) split_kernel(
    const float* __restrict__ src, __nv_bfloat16* __restrict__ hi,
    __nv_bfloat16* __restrict__ lo, int n4) {
  int i = blockIdx.x * blockDim.x + threadIdx.x;
  if (i >= n4) return;
  float4 v = ((const float4*)src)[i];
  __nv_bfloat16 h0 = __float2bfloat16(v.x);
  __nv_bfloat16 h1 = __float2bfloat16(v.y);
  __nv_bfloat16 h2 = __float2bfloat16(v.z);
  __nv_bfloat16 h3 = __float2bfloat16(v.w);
  __nv_bfloat162* hp = (__nv_bfloat162*)hi;
  __nv_bfloat162* lp = (__nv_bfloat162*)lo;
  hp[2 * i] = __nv_bfloat162(h0, h1);
  hp[2 * i + 1] = __nv_bfloat162(h2, h3);
  lp[2 * i] = __nv_bfloat162(__float2bfloat16(v.x - __bfloat162float(h0)),
                             __float2bfloat16(v.y - __bfloat162float(h1)));
  lp[2 * i + 1] = __nv_bfloat162(__float2bfloat16(v.z - __bfloat162float(h2)),
                                 __float2bfloat16(v.w - __bfloat162float(h3)));
}

__global__ void __launch_bounds__(256) split_w_kernel(
    const float* __restrict__ Wq, const float* __restrict__ Wk,
    const float* __restrict__ Wv, const float* __restrict__ Wo) {
  int slot = blockIdx.y;
  const float* W = (slot == 0) ? Wq : (slot == 1) ? Wk : (slot == 2) ? Wv : Wo;
  int i = blockIdx.x * blockDim.x + threadIdx.x;
  int n4 = DIMc * DIMc / 4;
  if (i >= n4) return;
  float4 v = ((const float4*)W)[i];
  __nv_bfloat16* hi = g_whi + (size_t)slot * DIMc * DIMc;
  __nv_bfloat16* lo = g_wlo + (size_t)slot * DIMc * DIMc;
  __nv_bfloat16 h0 = __float2bfloat16(v.x);
  __nv_bfloat16 h1 = __float2bfloat16(v.y);
  __nv_bfloat16 h2 = __float2bfloat16(v.z);
  __nv_bfloat16 h3 = __float2bfloat16(v.w);
  __nv_bfloat162* hp = (__nv_bfloat162*)hi;
  __nv_bfloat162* lp = (__nv_bfloat162*)lo;
  hp[2 * i] = __nv_bfloat162(h0, h1);
  hp[2 * i + 1] = __nv_bfloat162(h2, h3);
  lp[2 * i] = __nv_bfloat162(__float2bfloat16(v.x - __bfloat162float(h0)),
                             __float2bfloat16(v.y - __bfloat162float(h1)));
  lp[2 * i + 1] = __nv_bfloat162(__float2bfloat16(v.z - __bfloat162float(h2)),
                                 __float2bfloat16(v.w - __bfloat162float(h3)));
}

// ---------------- HMMA split-bf16 GEMM, warp tile 64x64 ---------------------
// CTA tile 128x128, 4 warps (2x2), 128 threads, k-chunk 32, 2-stage cp.async.
#define ASTRIDE_B 80
#define TILE_B (128 * ASTRIDE_B)
#define STAGE_B (4 * TILE_B)
#define G_SMEM (2 * STAGE_B)

__device__ __forceinline__ void load_stage(
    uint32_t sbase, const __nv_bfloat16* __restrict__ Ahi,
    const __nv_bfloat16* __restrict__ Alo, const __nv_bfloat16* __restrict__ Bhi,
    const __nv_bfloat16* __restrict__ Blo, int row0, int col0, int k0,
    int tid) {
  const __nv_bfloat16* srcs[4];
  srcs[0] = Ahi + (size_t)row0 * DIMc;
  srcs[1] = Alo + (size_t)row0 * DIMc;
  srcs[2] = Bhi + (size_t)col0 * DIMc;
  srcs[3] = Blo + (size_t)col0 * DIMc;
#pragma unroll
  for (int tbl = 0; tbl < 4; tbl++) {
    const __nv_bfloat16* s = srcs[tbl];
    uint32_t dst = sbase + tbl * TILE_B;
#pragma unroll
    for (int it = 0; it < 4; it++) {
      int idx = tid + it * 128;
      int row = idx >> 2, c = idx & 3;
      cpa16(dst + row * ASTRIDE_B + c * 16,
            s + (size_t)row * DIMc + k0 + c * 8);
    }
  }
}

// OUTS: 0 = fp32 C (+bias), 1 = bf16 hi/lo split (+bias), 2 = rope + split (+bias)
template <int OUTS>
__device__ __forceinline__ void gemm_tc_body(
    const __nv_bfloat16* __restrict__ Ahi, const __nv_bfloat16* __restrict__ Alo,
    const __nv_bfloat16* __restrict__ Whi, const __nv_bfloat16* __restrict__ Wlo,
    const float* __restrict__ bias, float* __restrict__ C,
    __nv_bfloat16* __restrict__ Chi, __nv_bfloat16* __restrict__ Clo) {
  extern __shared__ char smg[];
  uint32_t sb = smem_u32(smg);
  const int tid = threadIdx.x;
  const int lane = tid & 31, wid = tid >> 5;
  const int warpm = wid & 1, warpn = wid >> 1;
  const int row0 = blockIdx.y * 128, col0 = blockIdx.x * 128;

  float acc[4][8][4];
#pragma unroll
  for (int mt = 0; mt < 4; mt++)
#pragma unroll
    for (int j = 0; j < 8; j++)
#pragma unroll
      for (int c = 0; c < 4; c++) acc[mt][j][c] = 0.f;

  const int a_row = lane & 15, a_kof = (lane >> 4) * 8;
  const int b_n = (lane & 7) + ((lane >> 4) * 8);
  const int b_kof = ((lane >> 3) & 1) * 8;

  load_stage(sb, Ahi, Alo, Whi, Wlo, row0, col0, 0, tid);
  CP_COMMIT;

  const int T = DIMc / 32;
  for (int t = 0; t < T; t++) {
    if (t + 1 < T) {
      load_stage(sb + ((t + 1) & 1) * STAGE_B, Ahi, Alo, Whi, Wlo, row0, col0,
                 (t + 1) * 32, tid);
      CP_COMMIT;
      CP_WAIT1;
    } else {
      CP_WAIT0;
    }
    __syncthreads();

    uint32_t st = sb + (t & 1) * STAGE_B;
    uint32_t Ahs = st, Als = st + TILE_B, Bhs = st + 2 * TILE_B,
             Bls = st + 3 * TILE_B;
#pragma unroll
    for (int kk = 0; kk < 32; kk += 16) {
      uint32_t ah[4][4], al[4][4];
#pragma unroll
      for (int mt = 0; mt < 4; mt++) {
        int r = warpm * 64 + mt * 16 + a_row;
        uint32_t off = r * ASTRIDE_B + (kk + a_kof) * 2;
        ldm_x4(Ahs + off, ah[mt]);
        ldm_x4(Als + off, al[mt]);
      }
#pragma unroll
      for (int nt = 0; nt < 4; nt++) {
        uint32_t bh[4], bl[4];
        int n = warpn * 64 + nt * 16 + b_n;
        uint32_t off = n * ASTRIDE_B + (kk + b_kof) * 2;
        ldm_x4(Bhs + off, bh);
        ldm_x4(Bls + off, bl);
        // per-accumulator product order hh -> hl -> lh (bit-identical)
#pragma unroll
        for (int mt = 0; mt < 4; mt++) {
          mma16816(acc[mt][nt * 2 + 0], ah[mt], &bh[0]);
          mma16816(acc[mt][nt * 2 + 1], ah[mt], &bh[2]);
        }
#pragma unroll
        for (int mt = 0; mt < 4; mt++) {
          mma16816(acc[mt][nt * 2 + 0], ah[mt], &bl[0]);
          mma16816(acc[mt][nt * 2 + 1], ah[mt], &bl[2]);
        }
#pragma unroll
        for (int mt = 0; mt < 4; mt++) {
          mma16816(acc[mt][nt * 2 + 0], al[mt], &bh[0]);
          mma16816(acc[mt][nt * 2 + 1], al[mt], &bh[2]);
        }
      }
    }
    __syncthreads();
  }

  // ---------------- epilogues ----------------
  if (OUTS == 2) {
    // RoPE + split. Warp n-tile (64 cols) == one head; pairs (d, d+32) = (j, j+4).
#pragma unroll
    for (int mt = 0; mt < 4; mt++) {
      int r = row0 + warpm * 64 + mt * 16 + (lane >> 2);
      int sA = r & (Sc - 1);
#pragma unroll
      for (int j = 0; j < 4; j++) {
        int d = j * 8 + (lane & 3) * 2;  // 0..30, even
        int colA = col0 + warpn * 64 + d;
        float b0 = bias[colA], b1 = bias[colA + 1];
        float b2 = bias[colA + 32], b3 = bias[colA + 33];
#pragma unroll
        for (int half = 0; half < 2; half++) {
          int rr = r + half * 8;
          int ss = sA + half * 8;
          float cs0 = g_cs[ss * 32 + d], sn0 = g_sn[ss * 32 + d];
          float cs1 = g_cs[ss * 32 + d + 1], sn1 = g_sn[ss * 32 + d + 1];
          float q1a = acc[mt][j][2 * half + 0] + b0;
          float q1b = acc[mt][j][2 * half + 1] + b1;
          float q2a = acc[mt][j + 4][2 * half + 0] + b2;
          float q2b = acc[mt][j + 4][2 * half + 1] + b3;
          float o1a = fmaf(q1a, cs0, -q2a * sn0);
          float o2a = fmaf(q2a, cs0, q1a * sn0);
          float o1b = fmaf(q1b, cs1, -q2b * sn1);
          float o2b = fmaf(q2b, cs1, q1b * sn1);
          size_t offA = (size_t)rr * DIMc + colA;
          __nv_bfloat16 h1a = __float2bfloat16(o1a);
          __nv_bfloat16 h1b = __float2bfloat16(o1b);
          __nv_bfloat16 h2a = __float2bfloat16(o2a);
          __nv_bfloat16 h2b = __float2bfloat16(o2b);
          *(__nv_bfloat162*)(Chi + offA) = __nv_bfloat162(h1a, h1b);
          *(__nv_bfloat162*)(Clo + offA) =
              __nv_bfloat162(__float2bfloat16(o1a - __bfloat162float(h1a)),
                             __float2bfloat16(o1b - __bfloat162float(h1b)));
          *(__nv_bfloat162*)(Chi + offA + 32) = __nv_bfloat162(h2a, h2b);
          *(__nv_bfloat162*)(Clo + offA + 32) =
              __nv_bfloat162(__float2bfloat16(o2a - __bfloat162float(h2a)),
                             __float2bfloat16(o2b - __bfloat162float(h2b)));
        }
      }
    }
  } else {
#pragma unroll
    for (int mt = 0; mt < 4; mt++) {
#pragma unroll
      for (int j = 0; j < 8; j++) {
        int row = row0 + warpm * 64 + mt * 16 + (lane >> 2);
        int col = col0 + warpn * 64 + j * 8 + (lane & 3) * 2;
        float b0 = bias[col], b1 = bias[col + 1];
        float x0 = acc[mt][j][0] + b0, x1 = acc[mt][j][1] + b1;
        float y0 = acc[mt][j][2] + b0, y1 = acc[mt][j][3] + b1;
        if (OUTS == 1) {
          __nv_bfloat16 h0 = __float2bfloat16(x0), h1 = __float2bfloat16(x1);
          __nv_bfloat16 g0 = __float2bfloat16(y0), g1 = __float2bfloat16(y1);
          *(__nv_bfloat162*)(Chi + (size_t)row * DIMc + col) =
              __nv_bfloat162(h0, h1);
          *(__nv_bfloat162*)(Clo + (size_t)row * DIMc + col) = __nv_bfloat162(
              __float2bfloat16(x0 - __bfloat162float(h0)),
              __float2bfloat16(x1 - __bfloat162float(h1)));
          *(__nv_bfloat162*)(Chi + (size_t)(row + 8) * DIMc + col) =
              __nv_bfloat162(g0, g1);
          *(__nv_bfloat162*)(Clo + (size_t)(row + 8) * DIMc + col) =
              __nv_bfloat162(__float2bfloat16(y0 - __bfloat162float(g0)),
                             __float2bfloat16(y1 - __bfloat162float(g1)));
        } else {
          *(float2*)(C + (size_t)row * DIMc + col) = make_float2(x0, x1);
          *(float2*)(C + (size_t)(row + 8) * DIMc + col) = make_float2(y0, y1);
        }
      }
    }
  }
}

__global__ void __launch_bounds__(128, 2) gemm_tc_qkv(
    const float* __restrict__ bq, const float* __restrict__ bk,
    const float* __restrict__ bv) {
  int z = blockIdx.z;
  const __nv_bfloat16* Whi = g_whi + (size_t)z * DIMc * DIMc;
  const __nv_bfloat16* Wlo = g_wlo + (size_t)z * DIMc * DIMc;
  if (z == 0) {
    gemm_tc_body<2>(g_xhi, g_xlo, Whi, Wlo, bq, nullptr, g_qhi, g_qlo);
  } else if (z == 1) {
    gemm_tc_body<2>(g_xhi, g_xlo, Whi, Wlo, bk, nullptr, g_khi, g_klo);
  } else {
    gemm_tc_body<1>(g_xhi, g_xlo, Whi, Wlo, bv, nullptr, g_vhi, g_vlo);
  }
}

__global__ void __launch_bounds__(128, 2) gemm_tc_out(
    const float* __restrict__ bo, float* __restrict__ C) {
  const __nv_bfloat16* Whi = g_whi + (size_t)3 * DIMc * DIMc;
  const __nv_bfloat16* Wlo = g_wlo + (size_t)3 * DIMc * DIMc;
  gemm_tc_body<0>(g_ohi, g_olo, Whi, Wlo, bo, C, nullptr, nullptr);
}

// ---------------- RoPE table ------------------------------------------------
__global__ void rope_table_kernel() {
  int idx = blockIdx.x * blockDim.x + threadIdx.x;
  if (idx >= Sc * 32) return;
  int j = idx & 31;
  int s = idx >> 5;
  double freq = exp(-(double)j * (log(10000.0) / 32.0));
  double ang = (double)s * freq;
  g_cs[idx] = (float)cos(ang);
  g_sn[idx] = (float)sin(ang);
}

// ---------------- Flash attention, HMMA, double-buffered KV -----------------
#define FSTR 72
#define FB (FSTR * 2)
#define F_QH 0
#define F_QL 9216
#define F_KV0 18432
#define KV_STAGE_E 18432
#define F_SMEM_B ((18432 + 2 * 18432) * 2)

__device__ __forceinline__ void flash_kv_load(uint32_t stgA, size_t kvof,
                                              int tid) {
#pragma unroll
  for (int it = 0; it < 8; it++) {
    int idx = tid + it * 256;
    int arr = idx >> 9, rem = idx & 511;
    int row = rem >> 3, c = rem & 7;
    const __nv_bfloat16* src =
        (arr == 0) ? g_khi : (arr == 1) ? g_klo : (arr == 2) ? g_vhi : g_vlo;
    uint32_t dstA = stgA + arr * (4608 * 2);
    cpa16(dstA + row * FB + c * 16, src + kvof + (size_t)row * DIMc + c * 8);
  }
}

__global__ void __launch_bounds__(256, 2) flash_tc_kernel() {
  extern __shared__ __nv_bfloat16 sf[];
  uint32_t sbase = smem_u32(sf);
  const uint32_t QhA = sbase + F_QH * 2, QlA = sbase + F_QL * 2;

  const int tid = threadIdx.x, lane = tid & 31, w = tid >> 5;
  const int b = blockIdx.y >> 4, h = blockIdx.y & 15;
  const int q0 = blockIdx.x * 128;
  const size_t hof = (size_t)b * Sc * DIMc + h * DHc;

#pragma unroll
  for (int it = 0; it < 4; it++) {
    int idx = tid + it * 256;
    int row = idx >> 3, c = idx & 7;
    cpa16(QhA + row * FB + c * 16, g_qhi + hof + (size_t)(q0 + row) * DIMc + c * 8);
    cpa16(QlA + row * FB + c * 16, g_qlo + hof + (size_t)(q0 + row) * DIMc + c * 8);
  }
  CP_COMMIT;
  flash_kv_load(sbase + F_KV0 * 2, hof, tid);
  CP_COMMIT;
  CP_WAIT0;
  __syncthreads();

  const int a_row = lane & 15, a_kof = (lane >> 4) * 8;
  const int b_n = (lane & 7) + ((lane >> 4) * 8);
  const int b_kof = ((lane >> 3) & 1) * 8;
  uint32_t qh[4][4], ql[4][4];
#pragma unroll
  for (int kc = 0; kc < 4; kc++) {
    uint32_t off = (uint32_t)(w * 16 + a_row) * FB + (kc * 16 + a_kof) * 2;
    ldm_x4(QhA + off, qh[kc]);
    ldm_x4(QlA + off, ql[kc]);
  }

  float m0 = -INFINITY, m1 = -INFINITY, l0 = 0.f, l1 = 0.f;
  float acc[8][4];
#pragma unroll
  for (int dt = 0; dt < 8; dt++)
#pragma unroll
    for (int c = 0; c < 4; c++) acc[dt][c] = 0.f;

  const float scale = 0.125f;

  for (int t = 0; t < 16; t++) {
    if (t + 1 < 16) {
      __syncthreads();
      flash_kv_load(sbase + (F_KV0 + ((t + 1) & 1) * KV_STAGE_E) * 2,
                    hof + (size_t)(t + 1) * 64 * DIMc, tid);
      CP_COMMIT;
      CP_WAIT1;
    } else {
      CP_WAIT0;
    }
    __syncthreads();

    uint32_t stg = sbase + (F_KV0 + (t & 1) * KV_STAGE_E) * 2;
    uint32_t KhA = stg, KlA = stg + 4608 * 2, VhA = stg + 9216 * 2,
             VlA = stg + 13824 * 2;

    float s[8][4];
#pragma unroll
    for (int nt = 0; nt < 8; nt++)
#pragma unroll
      for (int c = 0; c < 4; c++) s[nt][c] = 0.f;
#pragma unroll
    for (int kc = 0; kc < 4; kc++) {
#pragma unroll
      for (int ngp = 0; ngp < 4; ngp += 2) {
        uint32_t bha[4], bla[4], bhb[4], blb[4];
        uint32_t offa = (uint32_t)(ngp * 16 + b_n) * FB + (kc * 16 + b_kof) * 2;
        uint32_t offb =
            (uint32_t)((ngp + 1) * 16 + b_n) * FB + (kc * 16 + b_kof) * 2;
        ldm_x4(KhA + offa, bha);
        ldm_x4(KlA + offa, bla);
        ldm_x4(KhA + offb, bhb);
        ldm_x4(KlA + offb, blb);
        float* c0 = s[2 * ngp + 0];
        float* c1 = s[2 * ngp + 1];
        float* c2 = s[2 * ngp + 2];
        float* c3 = s[2 * ngp + 3];
        mma16816(c0, qh[kc], &bha[0]);
        mma16816(c1, qh[kc], &bha[2]);
        mma16816(c2, qh[kc], &bhb[0]);
        mma16816(c3, qh[kc], &bhb[2]);
        mma16816(c0, qh[kc], &bla[0]);
        mma16816(c1, qh[kc], &bla[2]);
        mma16816(c2, qh[kc], &blb[0]);
        mma16816(c3, qh[kc], &blb[2]);
        mma16816(c0, ql[kc], &bha[0]);
        mma16816(c1, ql[kc], &bha[2]);
        mma16816(c2, ql[kc], &bhb[0]);
        mma16816(c3, ql[kc], &bhb[2]);
      }
    }

    float mx0 = -INFINITY, mx1 = -INFINITY;
#pragma unroll
    for (int nt = 0; nt < 8; nt++) {
      s[nt][0] *= scale; s[nt][1] *= scale;
      s[nt][2] *= scale; s[nt][3] *= scale;
      mx0 = fmaxf(mx0, fmaxf(s[nt][0], s[nt][1]));
      mx1 = fmaxf(mx1, fmaxf(s[nt][2], s[nt][3]));
    }
    mx0 = fmaxf(mx0, __shfl_xor_sync(0xffffffffu, mx0, 1));
    mx0 = fmaxf(mx0, __shfl_xor_sync(0xffffffffu, mx0, 2));
    mx1 = fmaxf(mx1, __shfl_xor_sync(0xffffffffu, mx1, 1));
    mx1 = fmaxf(mx1, __shfl_xor_sync(0xffffffffu, mx1, 2));
    float mn0 = fmaxf(m0, mx0), mn1 = fmaxf(m1, mx1);
    float corr0 = __expf(m0 - mn0), corr1 = __expf(m1 - mn1);
    m0 = mn0; m1 = mn1;
    float rs0 = 0.f, rs1 = 0.f;
#pragma unroll
    for (int nt = 0; nt < 8; nt++) {
      s[nt][0] = __expf(s[nt][0] - mn0);
      s[nt][1] = __expf(s[nt][1] - mn0);
      s[nt][2] = __expf(s[nt][2] - mn1);
      s[nt][3] = __expf(s[nt][3] - mn1);
      rs0 += s[nt][0] + s[nt][1];
      rs1 += s[nt][2] + s[nt][3];
    }
    rs0 += __shfl_xor_sync(0xffffffffu, rs0, 1);
    rs0 += __shfl_xor_sync(0xffffffffu, rs0, 2);
    rs1 += __shfl_xor_sync(0xffffffffu, rs1, 1);
    rs1 += __shfl_xor_sync(0xffffffffu, rs1, 2);
    l0 = l0 * corr0 + rs0;
    l1 = l1 * corr1 + rs1;

    uint32_t ph[4][4], pl[4][4];
#pragma unroll
    for (int kc = 0; kc < 4; kc++) {
      float* sa = s[2 * kc];
      float* sbn = s[2 * kc + 1];
      float r0a = __bfloat162float(__float2bfloat16(sa[0]));
      float r0b = __bfloat162float(__float2bfloat16(sa[1]));
      float r1a = __bfloat162float(__float2bfloat16(sa[2]));
      float r1b = __bfloat162float(__float2bfloat16(sa[3]));
      float n0a = __bfloat162float(__float2bfloat16(sbn[0]));
      float n0b = __bfloat162float(__float2bfloat16(sbn[1]));
      float n1a = __bfloat162float(__float2bfloat16(sbn[2]));
      float n1b = __bfloat162float(__float2bfloat16(sbn[3]));
      ph[kc][0] = packbf(sa[0], sa[1]);
      ph[kc][1] = packbf(sa[2], sa[3]);
      ph[kc][2] = packbf(sbn[0], sbn[1]);
      ph[kc][3] = packbf(sbn[2], sbn[3]);
      pl[kc][0] = packbf(sa[0] - r0a, sa[1] - r0b);
      pl[kc][1] = packbf(sa[2] - r1a, sa[3] - r1b);
      pl[kc][2] = packbf(sbn[0] - n0a, sbn[1] - n0b);
      pl[kc][3] = packbf(sbn[2] - n1a, sbn[3] - n1b);
    }

#pragma unroll
    for (int dt = 0; dt < 8; dt++) {
      acc[dt][0] *= corr0; acc[dt][1] *= corr0;
      acc[dt][2] *= corr1; acc[dt][3] *= corr1;
    }

#pragma unroll
    for (int kc = 0; kc < 4; kc++) {
#pragma unroll
      for (int ngp = 0; ngp < 4; ngp += 2) {
        uint32_t vha[4], vla[4], vhb[4], vlb[4];
        uint32_t offa = (uint32_t)(kc * 16 + (lane & 15)) * FB +
                        (ngp * 16 + (lane >> 4) * 8) * 2;
        uint32_t offb = (uint32_t)(kc * 16 + (lane & 15)) * FB +
                        ((ngp + 1) * 16 + (lane >> 4) * 8) * 2;
        ldm_x4_trans(VhA + offa, vha);
        ldm_x4_trans(VlA + offa, vla);
        ldm_x4_trans(VhA + offb, vhb);
        ldm_x4_trans(VlA + offb, vlb);
        float* c0 = acc[2 * ngp + 0];
        float* c1 = acc[2 * ngp + 1];
        float* c2 = acc[2 * ngp + 2];
        float* c3 = acc[2 * ngp + 3];
        mma16816(c0, ph[kc], &vha[0]);
        mma16816(c1, ph[kc], &vha[2]);
        mma16816(c2, ph[kc], &vhb[0]);
        mma16816(c3, ph[kc], &vhb[2]);
        mma16816(c0, ph[kc], &vla[0]);
        mma16816(c1, ph[kc], &vla[2]);
        mma16816(c2, ph[kc], &vlb[0]);
        mma16816(c3, ph[kc], &vlb[2]);
        mma16816(c0, pl[kc], &vha[0]);
        mma16816(c1, pl[kc], &vha[2]);
        mma16816(c2, pl[kc], &vhb[0]);
        mma16816(c3, pl[kc], &vhb[2]);
      }
    }
  }

  float inv0 = 1.f / l0, inv1 = 1.f / l1;
  int r0 = q0 + w * 16 + (lane >> 2);
#pragma unroll
  for (int dt = 0; dt < 8; dt++) {
    int col = h * DHc + dt * 8 + (lane & 3) * 2;
    float x0 = acc[dt][0] * inv0, x1 = acc[dt][1] * inv0;
    float y0 = acc[dt][2] * inv1, y1 = acc[dt][3] * inv1;
    size_t off0 = (size_t)(b * Sc + r0) * DIMc + col;
    size_t off1 = (size_t)(b * Sc + r0 + 8) * DIMc + col;
    __nv_bfloat16 h0 = __float2bfloat16(x0), h1 = __float2bfloat16(x1);
    __nv_bfloat16 g0 = __float2bfloat16(y0), g1 = __float2bfloat16(y1);
    *(__nv_bfloat162*)(g_ohi + off0) = __nv_bfloat162(h0, h1);
    *(__nv_bfloat162*)(g_olo + off0) =
        __nv_bfloat162(__float2bfloat16(x0 - __bfloat162float(h0)),
                       __float2bfloat16(x1 - __bfloat162float(h1)));
    *(__nv_bfloat162*)(g_ohi + off1) = __nv_bfloat162(g0, g1);
    *(__nv_bfloat162*)(g_olo + off1) =
        __nv_bfloat162(__float2bfloat16(y0 - __bfloat162float(g0)),
                       __float2bfloat16(y1 - __bfloat162float(g1)));
  }
}

// ----------------------------------------------------------------------------
extern "C" void kernel_launch(void* const* d_in, const int* in_sizes, int n_in,
                              void* d_out, int out_size) {
  const float* x = (const float*)d_in[0];
  const float* Wq = (const float*)d_in[1];
  const float* bq = (const float*)d_in[2];
  const float* Wk = (const float*)d_in[3];
  const float* bk = (const float*)d_in[4];
  const float* Wv = (const float*)d_in[5];
  const float* bv = (const float*)d_in[6];
  const float* Wo = (const float*)d_in[7];
  const float* bo = (const float*)d_in[8];
  float* out = (float*)d_out;

  __nv_bfloat16 *xhi, *xlo;
  cudaGetSymbolAddress((void**)&xhi, g_xhi);
  cudaGetSymbolAddress((void**)&xlo, g_xlo);

  cudaFuncSetAttribute(gemm_tc_qkv, cudaFuncAttributeMaxDynamicSharedMemorySize,
                       G_SMEM);
  cudaFuncSetAttribute(gemm_tc_out, cudaFuncAttributeMaxDynamicSharedMemorySize,
                       G_SMEM);
  cudaFuncSetAttribute(flash_tc_kernel,
                       cudaFuncAttributeMaxDynamicSharedMemorySize, F_SMEM_B);

  rope_table_kernel<<<(Sc * 32 + 255) / 256, 256>>>();

  int n4x = Mc * DIMc / 4;
  split_kernel<<<(n4x + 255) / 256, 256>>>(x, xhi, xlo, n4x);
  int n4w = DIMc * DIMc / 4;
  split_w_kernel<<<dim3((n4w + 255) / 256, 4), 256>>>(Wq, Wk, Wv, Wo);

  gemm_tc_qkv<<<dim3(DIMc / 128, Mc / 128, 3), 128, G_SMEM>>>(bq, bk, bv);

  flash_tc_kernel<<<dim3(Sc / 128, Bc * Hc), 256, F_SMEM_B>>>();

  gemm_tc_out<<<dim3(DIMc / 128, Mc / 128), 128, G_SMEM>>>(bo, out);
}

// round 16
// speedup vs baseline: 1.1915x; 1.1461x over previous
#include <cuda_runtime.h>
#include <cuda_bf16.h>
#include <cuda_fp16.h>
#include <math.h>
#include <stdint.h>

#define Bc 4
#define Sc 1024
#define DIMc 1024
#define Hc 16
#define DHc 64
#define Mc (Bc * Sc)

// ---------------- scratch (__device__ globals; no allocation allowed) -------
__device__ float g_cs[Sc * 32];
__device__ float g_sn[Sc * 32];
__device__ __nv_bfloat16 g_xhi[Mc * DIMc];
__device__ __nv_bfloat16 g_xlo[Mc * DIMc];
__device__ __nv_bfloat16 g_whi[4 * DIMc * DIMc];
__device__ __nv_bfloat16 g_wlo[4 * DIMc * DIMc];
__device__ __half g_qh[Mc * DIMc];
__device__ __half g_kh[Mc * DIMc];
__device__ __half g_kl[Mc * DIMc];
__device__ __half g_vh[Mc * DIMc];
__device__ __half g_vl[Mc * DIMc];
__device__ __nv_bfloat16 g_ohi[Mc * DIMc];
__device__ __nv_bfloat16 g_olo[Mc * DIMc];

// ---------------- PTX helpers (non-'a' features only) -----------------------
__device__ __forceinline__ uint32_t smem_u32(const void* p) {
  uint32_t a;
  asm("{ .reg .u64 t; cvta.to.shared.u64 t, %1; cvt.u32.u64 %0, t; }"
      : "=r"(a) : "l"(p));
  return a;
}

__device__ __forceinline__ void cpa16(uint32_t dst, const void* src) {
  asm volatile("cp.async.ca.shared.global [%0], [%1], 16;" ::"r"(dst),
               "l"(src));
}
#define CP_COMMIT asm volatile("cp.async.commit_group;" ::: "memory")
#define CP_WAIT1 asm volatile("cp.async.wait_group 1;" ::: "memory")
#define CP_WAIT0 asm volatile("cp.async.wait_group 0;" ::: "memory")

__device__ __forceinline__ void ldm_x4(uint32_t addr, uint32_t* r) {
  asm volatile(
      "ldmatrix.sync.aligned.m8n8.x4.shared.b16 {%0,%1,%2,%3}, [%4];"
      : "=r"(r[0]), "=r"(r[1]), "=r"(r[2]), "=r"(r[3])
      : "r"(addr));
}

__device__ __forceinline__ void ldm_x4_trans(uint32_t addr, uint32_t* r) {
  asm volatile(
      "ldmatrix.sync.aligned.m8n8.x4.trans.shared.b16 {%0,%1,%2,%3}, [%4];"
      : "=r"(r[0]), "=r"(r[1]), "=r"(r[2]), "=r"(r[3])
      : "r"(addr));
}

__device__ __forceinline__ void mma16816(float* c, const uint32_t* a,
                                         const uint32_t* b) {
  asm volatile(
      "mma.sync.aligned.m16n8k16.row.col.f32.bf16.bf16.f32 "
      "{%0,%1,%2,%3}, {%4,%5,%6,%7}, {%8,%9}, {%0,%1,%2,%3};"
      : "+f"(c[0]), "+f"(c[1]), "+f"(c[2]), "+f"(c[3])
      : "r"(a[0]), "r"(a[1]), "r"(a[2]), "r"(a[3]), "r"(b[0]), "r"(b[1]));
}

__device__ __forceinline__ void mma16816h(float* c, const uint32_t* a,
                                          const uint32_t* b) {
  asm volatile(
      "mma.sync.aligned.m16n8k16.row.col.f32.f16.f16.f32 "
      "{%0,%1,%2,%3}, {%4,%5,%6,%7}, {%8,%9}, {%0,%1,%2,%3};"
      : "+f"(c[0]), "+f"(c[1]), "+f"(c[2]), "+f"(c[3])
      : "r"(a[0]), "r"(a[1]), "r"(a[2]), "r"(a[3]), "r"(b[0]), "r"(b[1]));
}

__device__ __forceinline__ uint32_t packh(float a, float b) {
  __half2 t = __floats2half2_rn(a, b);
  return *(uint32_t*)&t;
}

// ---------------- split kernels (fp32 -> bf16 hi/lo) ------------------------
__global__ void __launch_bounds__(256) split_kernel(
    const float* __restrict__ src, __nv_bfloat16* __restrict__ hi,
    __nv_bfloat16* __restrict__ lo, int n4) {
  int i = blockIdx.x * blockDim.x + threadIdx.x;
  if (i >= n4) return;
  float4 v = ((const float4*)src)[i];
  __nv_bfloat16 h0 = __float2bfloat16(v.x);
  __nv_bfloat16 h1 = __float2bfloat16(v.y);
  __nv_bfloat16 h2 = __float2bfloat16(v.z);
  __nv_bfloat16 h3 = __float2bfloat16(v.w);
  __nv_bfloat162* hp = (__nv_bfloat162*)hi;
  __nv_bfloat162* lp = (__nv_bfloat162*)lo;
  hp[2 * i] = __nv_bfloat162(h0, h1);
  hp[2 * i + 1] = __nv_bfloat162(h2, h3);
  lp[2 * i] = __nv_bfloat162(__float2bfloat16(v.x - __bfloat162float(h0)),
                             __float2bfloat16(v.y - __bfloat162float(h1)));
  lp[2 * i + 1] = __nv_bfloat162(__float2bfloat16(v.z - __bfloat162float(h2)),
                                 __float2bfloat16(v.w - __bfloat162float(h3)));
}

__global__ void __launch_bounds__(256) split_w_kernel(
    const float* __restrict__ Wq, const float* __restrict__ Wk,
    const float* __restrict__ Wv, const float* __restrict__ Wo) {
  int slot = blockIdx.y;
  const float* W = (slot == 0) ? Wq : (slot == 1) ? Wk : (slot == 2) ? Wv : Wo;
  int i = blockIdx.x * blockDim.x + threadIdx.x;
  int n4 = DIMc * DIMc / 4;
  if (i >= n4) return;
  float4 v = ((const float4*)W)[i];
  __nv_bfloat16* hi = g_whi + (size_t)slot * DIMc * DIMc;
  __nv_bfloat16* lo = g_wlo + (size_t)slot * DIMc * DIMc;
  __nv_bfloat16 h0 = __float2bfloat16(v.x);
  __nv_bfloat16 h1 = __float2bfloat16(v.y);
  __nv_bfloat16 h2 = __float2bfloat16(v.z);
  __nv_bfloat16 h3 = __float2bfloat16(v.w);
  __nv_bfloat162* hp = (__nv_bfloat162*)hi;
  __nv_bfloat162* lp = (__nv_bfloat162*)lo;
  hp[2 * i] = __nv_bfloat162(h0, h1);
  hp[2 * i + 1] = __nv_bfloat162(h2, h3);
  lp[2 * i] = __nv_bfloat162(__float2bfloat16(v.x - __bfloat162float(h0)),
                             __float2bfloat16(v.y - __bfloat162float(h1)));
  lp[2 * i + 1] = __nv_bfloat162(__float2bfloat16(v.z - __bfloat162float(h2)),
                                 __float2bfloat16(v.w - __bfloat162float(h3)));
}

// ---------------- HMMA split-bf16 GEMM, warp tile 64x64 ---------------------
// CTA tile 128x128, 4 warps (2x2), 128 threads, k-chunk 32, 2-stage cp.async.
#define ASTRIDE_B 80
#define TILE_B (128 * ASTRIDE_B)
#define STAGE_B (4 * TILE_B)
#define G_SMEM (2 * STAGE_B)

__device__ __forceinline__ void load_stage(
    uint32_t sbase, const __nv_bfloat16* __restrict__ Ahi,
    const __nv_bfloat16* __restrict__ Alo, const __nv_bfloat16* __restrict__ Bhi,
    const __nv_bfloat16* __restrict__ Blo, int row0, int col0, int k0,
    int tid) {
  const __nv_bfloat16* srcs[4];
  srcs[0] = Ahi + (size_t)row0 * DIMc;
  srcs[1] = Alo + (size_t)row0 * DIMc;
  srcs[2] = Bhi + (size_t)col0 * DIMc;
  srcs[3] = Blo + (size_t)col0 * DIMc;
#pragma unroll
  for (int tbl = 0; tbl < 4; tbl++) {
    const __nv_bfloat16* s = srcs[tbl];
    uint32_t dst = sbase + tbl * TILE_B;
#pragma unroll
    for (int it = 0; it < 4; it++) {
      int idx = tid + it * 128;
      int row = idx >> 2, c = idx & 3;
      cpa16(dst + row * ASTRIDE_B + c * 16,
            s + (size_t)row * DIMc + k0 + c * 8);
    }
  }
}

// OUTS: 0 = fp32 C (+bias)            [out proj]
//       1 = fp16 hi/lo split (+bias)  [V]
//       2 = rope + fp16 single        [Q]
//       3 = rope + fp16 hi/lo         [K]
template <int OUTS>
__device__ __forceinline__ void gemm_tc_body(
    const __nv_bfloat16* __restrict__ Ahi, const __nv_bfloat16* __restrict__ Alo,
    const __nv_bfloat16* __restrict__ Whi, const __nv_bfloat16* __restrict__ Wlo,
    const float* __restrict__ bias, float* __restrict__ C,
    __half* __restrict__ Hhi, __half* __restrict__ Hlo) {
  extern __shared__ char smg[];
  uint32_t sb = smem_u32(smg);
  const int tid = threadIdx.x;
  const int lane = tid & 31, wid = tid >> 5;
  const int warpm = wid & 1, warpn = wid >> 1;
  const int row0 = blockIdx.y * 128, col0 = blockIdx.x * 128;

  float acc[4][8][4];
#pragma unroll
  for (int mt = 0; mt < 4; mt++)
#pragma unroll
    for (int j = 0; j < 8; j++)
#pragma unroll
      for (int c = 0; c < 4; c++) acc[mt][j][c] = 0.f;

  const int a_row = lane & 15, a_kof = (lane >> 4) * 8;
  const int b_n = (lane & 7) + ((lane >> 4) * 8);
  const int b_kof = ((lane >> 3) & 1) * 8;

  load_stage(sb, Ahi, Alo, Whi, Wlo, row0, col0, 0, tid);
  CP_COMMIT;

  const int T = DIMc / 32;
  for (int t = 0; t < T; t++) {
    if (t + 1 < T) {
      load_stage(sb + ((t + 1) & 1) * STAGE_B, Ahi, Alo, Whi, Wlo, row0, col0,
                 (t + 1) * 32, tid);
      CP_COMMIT;
      CP_WAIT1;
    } else {
      CP_WAIT0;
    }
    __syncthreads();

    uint32_t st = sb + (t & 1) * STAGE_B;
    uint32_t Ahs = st, Als = st + TILE_B, Bhs = st + 2 * TILE_B,
             Bls = st + 3 * TILE_B;
#pragma unroll
    for (int kk = 0; kk < 32; kk += 16) {
      uint32_t ah[4][4], al[4][4];
#pragma unroll
      for (int mt = 0; mt < 4; mt++) {
        int r = warpm * 64 + mt * 16 + a_row;
        uint32_t off = r * ASTRIDE_B + (kk + a_kof) * 2;
        ldm_x4(Ahs + off, ah[mt]);
        ldm_x4(Als + off, al[mt]);
      }
#pragma unroll
      for (int nt = 0; nt < 4; nt++) {
        uint32_t bh[4], bl[4];
        int n = warpn * 64 + nt * 16 + b_n;
        uint32_t off = n * ASTRIDE_B + (kk + b_kof) * 2;
        ldm_x4(Bhs + off, bh);
        ldm_x4(Bls + off, bl);
        // per-accumulator product order hh -> hl -> lh (bit-identical)
#pragma unroll
        for (int mt = 0; mt < 4; mt++) {
          mma16816(acc[mt][nt * 2 + 0], ah[mt], &bh[0]);
          mma16816(acc[mt][nt * 2 + 1], ah[mt], &bh[2]);
        }
#pragma unroll
        for (int mt = 0; mt < 4; mt++) {
          mma16816(acc[mt][nt * 2 + 0], ah[mt], &bl[0]);
          mma16816(acc[mt][nt * 2 + 1], ah[mt], &bl[2]);
        }
#pragma unroll
        for (int mt = 0; mt < 4; mt++) {
          mma16816(acc[mt][nt * 2 + 0], al[mt], &bh[0]);
          mma16816(acc[mt][nt * 2 + 1], al[mt], &bh[2]);
        }
      }
    }
    __syncthreads();
  }

  // ---------------- epilogues ----------------
  if (OUTS == 2 || OUTS == 3) {
    // RoPE + fp16. Warp n-tile (64 cols) == one head; pairs (d, d+32) = (j, j+4).
#pragma unroll
    for (int mt = 0; mt < 4; mt++) {
      int r = row0 + warpm * 64 + mt * 16 + (lane >> 2);
      int sA = r & (Sc - 1);
#pragma unroll
      for (int j = 0; j < 4; j++) {
        int d = j * 8 + (lane & 3) * 2;  // 0..30, even
        int colA = col0 + warpn * 64 + d;
        float b0 = bias[colA], b1 = bias[colA + 1];
        float b2 = bias[colA + 32], b3 = bias[colA + 33];
#pragma unroll
        for (int half_ = 0; half_ < 2; half_++) {
          int rr = r + half_ * 8;
          int ss = sA + half_ * 8;
          float cs0 = g_cs[ss * 32 + d], sn0 = g_sn[ss * 32 + d];
          float cs1 = g_cs[ss * 32 + d + 1], sn1 = g_sn[ss * 32 + d + 1];
          float q1a = acc[mt][j][2 * half_ + 0] + b0;
          float q1b = acc[mt][j][2 * half_ + 1] + b1;
          float q2a = acc[mt][j + 4][2 * half_ + 0] + b2;
          float q2b = acc[mt][j + 4][2 * half_ + 1] + b3;
          float o1a = fmaf(q1a, cs0, -q2a * sn0);
          float o2a = fmaf(q2a, cs0, q1a * sn0);
          float o1b = fmaf(q1b, cs1, -q2b * sn1);
          float o2b = fmaf(q2b, cs1, q1b * sn1);
          size_t offA = (size_t)rr * DIMc + colA;
          __half h1a = __float2half(o1a), h1b = __float2half(o1b);
          __half h2a = __float2half(o2a), h2b = __float2half(o2b);
          *(__half2*)(Hhi + offA) = __half2(h1a, h1b);
          *(__half2*)(Hhi + offA + 32) = __half2(h2a, h2b);
          if (OUTS == 3) {
            *(__half2*)(Hlo + offA) =
                __half2(__float2half(o1a - __half2float(h1a)),
                        __float2half(o1b - __half2float(h1b)));
            *(__half2*)(Hlo + offA + 32) =
                __half2(__float2half(o2a - __half2float(h2a)),
                        __float2half(o2b - __half2float(h2b)));
          }
        }
      }
    }
  } else {
#pragma unroll
    for (int mt = 0; mt < 4; mt++) {
#pragma unroll
      for (int j = 0; j < 8; j++) {
        int row = row0 + warpm * 64 + mt * 16 + (lane >> 2);
        int col = col0 + warpn * 64 + j * 8 + (lane & 3) * 2;
        float b0 = bias[col], b1 = bias[col + 1];
        float x0 = acc[mt][j][0] + b0, x1 = acc[mt][j][1] + b1;
        float y0 = acc[mt][j][2] + b0, y1 = acc[mt][j][3] + b1;
        if (OUTS == 1) {
          __half h0 = __float2half(x0), h1 = __float2half(x1);
          __half g0 = __float2half(y0), g1 = __float2half(y1);
          *(__half2*)(Hhi + (size_t)row * DIMc + col) = __half2(h0, h1);
          *(__half2*)(Hlo + (size_t)row * DIMc + col) =
              __half2(__float2half(x0 - __half2float(h0)),
                      __float2half(x1 - __half2float(h1)));
          *(__half2*)(Hhi + (size_t)(row + 8) * DIMc + col) = __half2(g0, g1);
          *(__half2*)(Hlo + (size_t)(row + 8) * DIMc + col) =
              __half2(__float2half(y0 - __half2float(g0)),
                      __float2half(y1 - __half2float(g1)));
        } else {
          *(float2*)(C + (size_t)row * DIMc + col) = make_float2(x0, x1);
          *(float2*)(C + (size_t)(row + 8) * DIMc + col) = make_float2(y0, y1);
        }
      }
    }
  }
}

__global__ void __launch_bounds__(128, 2) gemm_tc_qkv(
    const float* __restrict__ bq, const float* __restrict__ bk,
    const float* __restrict__ bv) {
  int z = blockIdx.z;
  const __nv_bfloat16* Whi = g_whi + (size_t)z * DIMc * DIMc;
  const __nv_bfloat16* Wlo = g_wlo + (size_t)z * DIMc * DIMc;
  if (z == 0) {
    gemm_tc_body<2>(g_xhi, g_xlo, Whi, Wlo, bq, nullptr, g_qh, nullptr);
  } else if (z == 1) {
    gemm_tc_body<3>(g_xhi, g_xlo, Whi, Wlo, bk, nullptr, g_kh, g_kl);
  } else {
    gemm_tc_body<1>(g_xhi, g_xlo, Whi, Wlo, bv, nullptr, g_vh, g_vl);
  }
}

__global__ void __launch_bounds__(128, 2) gemm_tc_out(
    const float* __restrict__ bo, float* __restrict__ C) {
  const __nv_bfloat16* Whi = g_whi + (size_t)3 * DIMc * DIMc;
  const __nv_bfloat16* Wlo = g_wlo + (size_t)3 * DIMc * DIMc;
  gemm_tc_body<0>(g_ohi, g_olo, Whi, Wlo, bo, C, nullptr, nullptr);
}

// ---------------- RoPE table ------------------------------------------------
__global__ void rope_table_kernel() {
  int idx = blockIdx.x * blockDim.x + threadIdx.x;
  if (idx >= Sc * 32) return;
  int j = idx & 31;
  int s = idx >> 5;
  double freq = exp(-(double)j * (log(10000.0) / 32.0));
  double ang = (double)s * freq;
  g_cs[idx] = (float)cos(ang);
  g_sn[idx] = (float)sin(ang);
}

// ---------------- Flash attention, fp16 2-product, double-buffered KV -------
// Q: fp16 single (Qh). K,V: fp16 hi/lo. S = Qh*Kh + Qh*Kl; O += Ph*Vh + Ph*Vl.
#define FSTR 72
#define FB (FSTR * 2)
#define F_QH 0
#define F_KV0 9216
#define KV_STAGE_E 18432
#define F_SMEM_B ((9216 + 2 * 18432) * 2)  // 92160 B

__device__ __forceinline__ void flash_kv_load(uint32_t stgA, size_t kvof,
                                              int tid) {
#pragma unroll
  for (int it = 0; it < 8; it++) {
    int idx = tid + it * 256;
    int arr = idx >> 9, rem = idx & 511;
    int row = rem >> 3, c = rem & 7;
    const __half* src =
        (arr == 0) ? g_kh : (arr == 1) ? g_kl : (arr == 2) ? g_vh : g_vl;
    uint32_t dstA = stgA + arr * (4608 * 2);
    cpa16(dstA + row * FB + c * 16, src + kvof + (size_t)row * DIMc + c * 8);
  }
}

__global__ void __launch_bounds__(256, 2) flash_tc_kernel() {
  extern __shared__ __half sf[];
  uint32_t sbase = smem_u32(sf);
  const uint32_t QhA = sbase + F_QH * 2;

  const int tid = threadIdx.x, lane = tid & 31, w = tid >> 5;
  const int b = blockIdx.y >> 4, h = blockIdx.y & 15;
  const int q0 = blockIdx.x * 128;
  const size_t hof = (size_t)b * Sc * DIMc + h * DHc;

  // Q tile (fp16 single) via cp.async: 128 rows x 8 chunks
#pragma unroll
  for (int it = 0; it < 4; it++) {
    int idx = tid + it * 256;
    int row = idx >> 3, c = idx & 7;
    cpa16(QhA + row * FB + c * 16, g_qh + hof + (size_t)(q0 + row) * DIMc + c * 8);
  }
  CP_COMMIT;
  flash_kv_load(sbase + F_KV0 * 2, hof, tid);
  CP_COMMIT;
  CP_WAIT0;
  __syncthreads();

  const int a_row = lane & 15, a_kof = (lane >> 4) * 8;
  const int b_n = (lane & 7) + ((lane >> 4) * 8);
  const int b_kof = ((lane >> 3) & 1) * 8;
  uint32_t qh[4][4];
#pragma unroll
  for (int kc = 0; kc < 4; kc++) {
    uint32_t off = (uint32_t)(w * 16 + a_row) * FB + (kc * 16 + a_kof) * 2;
    ldm_x4(QhA + off, qh[kc]);
  }

  float m0 = -INFINITY, m1 = -INFINITY, l0 = 0.f, l1 = 0.f;
  float acc[8][4];
#pragma unroll
  for (int dt = 0; dt < 8; dt++)
#pragma unroll
    for (int c = 0; c < 4; c++) acc[dt][c] = 0.f;

  const float scale = 0.125f;

  for (int t = 0; t < 16; t++) {
    if (t + 1 < 16) {
      __syncthreads();
      flash_kv_load(sbase + (F_KV0 + ((t + 1) & 1) * KV_STAGE_E) * 2,
                    hof + (size_t)(t + 1) * 64 * DIMc, tid);
      CP_COMMIT;
      CP_WAIT1;
    } else {
      CP_WAIT0;
    }
    __syncthreads();

    uint32_t stg = sbase + (F_KV0 + (t & 1) * KV_STAGE_E) * 2;
    uint32_t KhA = stg, KlA = stg + 4608 * 2, VhA = stg + 9216 * 2,
             VlA = stg + 13824 * 2;

    // ---- S = Qh * (Kh + Kl)   (2 products)
    float s[8][4];
#pragma unroll
    for (int nt = 0; nt < 8; nt++)
#pragma unroll
      for (int c = 0; c < 4; c++) s[nt][c] = 0.f;
#pragma unroll
    for (int kc = 0; kc < 4; kc++) {
#pragma unroll
      for (int ngp = 0; ngp < 4; ngp += 2) {
        uint32_t bha[4], bla[4], bhb[4], blb[4];
        uint32_t offa = (uint32_t)(ngp * 16 + b_n) * FB + (kc * 16 + b_kof) * 2;
        uint32_t offb =
            (uint32_t)((ngp + 1) * 16 + b_n) * FB + (kc * 16 + b_kof) * 2;
        ldm_x4(KhA + offa, bha);
        ldm_x4(KlA + offa, bla);
        ldm_x4(KhA + offb, bhb);
        ldm_x4(KlA + offb, blb);
        float* c0 = s[2 * ngp + 0];
        float* c1 = s[2 * ngp + 1];
        float* c2 = s[2 * ngp + 2];
        float* c3 = s[2 * ngp + 3];
        mma16816h(c0, qh[kc], &bha[0]);
        mma16816h(c1, qh[kc], &bha[2]);
        mma16816h(c2, qh[kc], &bhb[0]);
        mma16816h(c3, qh[kc], &bhb[2]);
        mma16816h(c0, qh[kc], &bla[0]);
        mma16816h(c1, qh[kc], &bla[2]);
        mma16816h(c2, qh[kc], &blb[0]);
        mma16816h(c3, qh[kc], &blb[2]);
      }
    }

    // ---- online softmax
    float mx0 = -INFINITY, mx1 = -INFINITY;
#pragma unroll
    for (int nt = 0; nt < 8; nt++) {
      s[nt][0] *= scale; s[nt][1] *= scale;
      s[nt][2] *= scale; s[nt][3] *= scale;
      mx0 = fmaxf(mx0, fmaxf(s[nt][0], s[nt][1]));
      mx1 = fmaxf(mx1, fmaxf(s[nt][2], s[nt][3]));
    }
    mx0 = fmaxf(mx0, __shfl_xor_sync(0xffffffffu, mx0, 1));
    mx0 = fmaxf(mx0, __shfl_xor_sync(0xffffffffu, mx0, 2));
    mx1 = fmaxf(mx1, __shfl_xor_sync(0xffffffffu, mx1, 1));
    mx1 = fmaxf(mx1, __shfl_xor_sync(0xffffffffu, mx1, 2));
    float mn0 = fmaxf(m0, mx0), mn1 = fmaxf(m1, mx1);
    float corr0 = __expf(m0 - mn0), corr1 = __expf(m1 - mn1);
    m0 = mn0; m1 = mn1;
    float rs0 = 0.f, rs1 = 0.f;
#pragma unroll
    for (int nt = 0; nt < 8; nt++) {
      s[nt][0] = __expf(s[nt][0] - mn0);
      s[nt][1] = __expf(s[nt][1] - mn0);
      s[nt][2] = __expf(s[nt][2] - mn1);
      s[nt][3] = __expf(s[nt][3] - mn1);
      rs0 += s[nt][0] + s[nt][1];
      rs1 += s[nt][2] + s[nt][3];
    }
    rs0 += __shfl_xor_sync(0xffffffffu, rs0, 1);
    rs0 += __shfl_xor_sync(0xffffffffu, rs0, 2);
    rs1 += __shfl_xor_sync(0xffffffffu, rs1, 1);
    rs1 += __shfl_xor_sync(0xffffffffu, rs1, 2);
    l0 = l0 * corr0 + rs0;
    l1 = l1 * corr1 + rs1;

    // P fragments (fp16 single)
    uint32_t ph[4][4];
#pragma unroll
    for (int kc = 0; kc < 4; kc++) {
      float* sa = s[2 * kc];
      float* sbn = s[2 * kc + 1];
      ph[kc][0] = packh(sa[0], sa[1]);
      ph[kc][1] = packh(sa[2], sa[3]);
      ph[kc][2] = packh(sbn[0], sbn[1]);
      ph[kc][3] = packh(sbn[2], sbn[3]);
    }

#pragma unroll
    for (int dt = 0; dt < 8; dt++) {
      acc[dt][0] *= corr0; acc[dt][1] *= corr0;
      acc[dt][2] *= corr1; acc[dt][3] *= corr1;
    }

    // ---- O += Ph * (Vh + Vl)   (2 products), trans fragments
#pragma unroll
    for (int kc = 0; kc < 4; kc++) {
#pragma unroll
      for (int ngp = 0; ngp < 4; ngp += 2) {
        uint32_t vha[4], vla[4], vhb[4], vlb[4];
        uint32_t offa = (uint32_t)(kc * 16 + (lane & 15)) * FB +
                        (ngp * 16 + (lane >> 4) * 8) * 2;
        uint32_t offb = (uint32_t)(kc * 16 + (lane & 15)) * FB +
                        ((ngp + 1) * 16 + (lane >> 4) * 8) * 2;
        ldm_x4_trans(VhA + offa, vha);
        ldm_x4_trans(VlA + offa, vla);
        ldm_x4_trans(VhA + offb, vhb);
        ldm_x4_trans(VlA + offb, vlb);
        float* c0 = acc[2 * ngp + 0];
        float* c1 = acc[2 * ngp + 1];
        float* c2 = acc[2 * ngp + 2];
        float* c3 = acc[2 * ngp + 3];
        mma16816h(c0, ph[kc], &vha[0]);
        mma16816h(c1, ph[kc], &vha[2]);
        mma16816h(c2, ph[kc], &vhb[0]);
        mma16816h(c3, ph[kc], &vhb[2]);
        mma16816h(c0, ph[kc], &vla[0]);
        mma16816h(c1, ph[kc], &vla[2]);
        mma16816h(c2, ph[kc], &vlb[0]);
        mma16816h(c3, ph[kc], &vlb[2]);
      }
    }
  }

  // ---- Writeback as bf16 hi/lo (consumed by gemm_tc_out, bf16-3)
  float inv0 = 1.f / l0, inv1 = 1.f / l1;
  int r0 = q0 + w * 16 + (lane >> 2);
#pragma unroll
  for (int dt = 0; dt < 8; dt++) {
    int col = h * DHc + dt * 8 + (lane & 3) * 2;
    float x0 = acc[dt][0] * inv0, x1 = acc[dt][1] * inv0;
    float y0 = acc[dt][2] * inv1, y1 = acc[dt][3] * inv1;
    size_t off0 = (size_t)(b * Sc + r0) * DIMc + col;
    size_t off1 = (size_t)(b * Sc + r0 + 8) * DIMc + col;
    __nv_bfloat16 h0 = __float2bfloat16(x0), h1 = __float2bfloat16(x1);
    __nv_bfloat16 g0 = __float2bfloat16(y0), g1 = __float2bfloat16(y1);
    *(__nv_bfloat162*)(g_ohi + off0) = __nv_bfloat162(h0, h1);
    *(__nv_bfloat162*)(g_olo + off0) =
        __nv_bfloat162(__float2bfloat16(x0 - __bfloat162float(h0)),
                       __float2bfloat16(x1 - __bfloat162float(h1)));
    *(__nv_bfloat162*)(g_ohi + off1) = __nv_bfloat162(g0, g1);
    *(__nv_bfloat162*)(g_olo + off1) =
        __nv_bfloat162(__float2bfloat16(y0 - __bfloat162float(g0)),
                       __float2bfloat16(y1 - __bfloat162float(g1)));
  }
}

// ----------------------------------------------------------------------------
extern "C" void kernel_launch(void* const* d_in, const int* in_sizes, int n_in,
                              void* d_out, int out_size) {
  const float* x = (const float*)d_in[0];
  const float* Wq = (const float*)d_in[1];
  const float* bq = (const float*)d_in[2];
  const float* Wk = (const float*)d_in[3];
  const float* bk = (const float*)d_in[4];
  const float* Wv = (const float*)d_in[5];
  const float* bv = (const float*)d_in[6];
  const float* Wo = (const float*)d_in[7];
  const float* bo = (const float*)d_in[8];
  float* out = (float*)d_out;

  __nv_bfloat16 *xhi, *xlo;
  cudaGetSymbolAddress((void**)&xhi, g_xhi);
  cudaGetSymbolAddress((void**)&xlo, g_xlo);

  cudaFuncSetAttribute(gemm_tc_qkv, cudaFuncAttributeMaxDynamicSharedMemorySize,
                       G_SMEM);
  cudaFuncSetAttribute(gemm_tc_out, cudaFuncAttributeMaxDynamicSharedMemorySize,
                       G_SMEM);
  cudaFuncSetAttribute(flash_tc_kernel,
                       cudaFuncAttributeMaxDynamicSharedMemorySize, F_SMEM_B);

  rope_table_kernel<<<(Sc * 32 + 255) / 256, 256>>>();

  int n4x = Mc * DIMc / 4;
  split_kernel<<<(n4x + 255) / 256, 256>>>(x, xhi, xlo, n4x);
  int n4w = DIMc * DIMc / 4;
  split_w_kernel<<<dim3((n4w + 255) / 256, 4), 256>>>(Wq, Wk, Wv, Wo);

  gemm_tc_qkv<<<dim3(DIMc / 128, Mc / 128, 3), 128, G_SMEM>>>(bq, bk, bv);

  flash_tc_kernel<<<dim3(Sc / 128, Bc * Hc), 256, F_SMEM_B>>>();

  gemm_tc_out<<<dim3(DIMc / 128, Mc / 128), 128, G_SMEM>>>(bo, out);
}